// round 10
// baseline (speedup 1.0000x reference)
#include <cuda_runtime.h>
#include <cstdint>

// ---------------------------------------------------------------------------
// Problem constants
// ---------------------------------------------------------------------------
#define BATCH 64
#define SEQ   512
#define DIM   768
#define BD    (BATCH * DIM)          // 49152
#define R192  192
#define KDIM  1536
#define PREDK 2304

#define KS_FC1  12                   // 1536 = 12 * 128
#define KS_GATE 8                    // 1536 = 8 * 192
#define KS_PRED 12                   // 2304 = 12 * 192

#define FC1_MN  (R192 * 512)         // 98304
#define GATE_MN (R192 * 768)         // 147456
#define PRED_MN (BATCH * 512)        // 32768

// smem: per worker 2 stages x (As[32][72] + Bs[32][72]) in floats
#define AS_PITCH 72
#define AS_F     (32 * AS_PITCH)     // 2304
#define BS_F     (32 * AS_PITCH)     // 2304
#define STAGE_F  (AS_F + BS_F)       // 4608
#define WORKER_F (2 * STAGE_F)       // 9216
#define TOTAL_SMEM_B (2 * WORKER_F * 4)   // 73728 bytes

// ---------------------------------------------------------------------------
// Device scratch
// ---------------------------------------------------------------------------
__device__ float g_ent  [BATCH * PREDK];
__device__ float g_e    [3 * BD];              // entity state, in-place
__device__ float g_X1   [R192 * KDIM];         // fc1 input  [eA | eB]
__device__ float g_X2   [R192 * KDIM];         // gate input [u  | e ]
__device__ float g_pfc1 [KS_FC1  * FC1_MN];
__device__ float g_pgate[KS_GATE * GATE_MN];
__device__ float g_ppred[KS_PRED * PRED_MN];
__device__ float g_scorep[576];                // maxpool dot partials [bk*3+q]

// tree grid barrier state (zero-initialized; each barrier restores zeros)
__device__ unsigned int g_leaf[8];
__device__ unsigned int g_root = 0;
__device__ unsigned int g_bar_gen = 0;

// ---------------------------------------------------------------------------
// Helpers
// ---------------------------------------------------------------------------
__device__ __forceinline__ float sigmoidf(float x) {
    return 1.0f / (1.0f + expf(-x));
}
__device__ __forceinline__ float4 ldcg4(const float* p) {
    return __ldcg(reinterpret_cast<const float4*>(p));
}
__device__ __forceinline__ void stcg4(float* p, float4 v) {
    __stcg(reinterpret_cast<float4*>(p), v);
}
__device__ __forceinline__ void stcg2(float* p, float2 v) {
    __stcg(reinterpret_cast<float2*>(p), v);
}
__device__ __forceinline__ float4 ldg4(const float* p) {
    return __ldg(reinterpret_cast<const float4*>(p));
}
__device__ __forceinline__ float f2tf32f(float x) {
    uint32_t r;
    asm("cvt.rna.tf32.f32 %0, %1;" : "=r"(r) : "f"(x));
    return __uint_as_float(r);
}
__device__ __forceinline__ void mma_tf32(float* d,
    uint32_t a0, uint32_t a1, uint32_t a2, uint32_t a3,
    uint32_t b0, uint32_t b1)
{
    asm volatile(
        "mma.sync.aligned.m16n8k8.row.col.f32.tf32.tf32.f32 "
        "{%0,%1,%2,%3}, {%4,%5,%6,%7}, {%8,%9}, {%0,%1,%2,%3};"
        : "+f"(d[0]), "+f"(d[1]), "+f"(d[2]), "+f"(d[3])
        : "r"(a0), "r"(a1), "r"(a2), "r"(a3), "r"(b0), "r"(b1));
}
// per-half (256-thread) named barrier: ids 1 and 2
__device__ __forceinline__ void wbar(int half) {
    asm volatile("bar.sync %0, 256;" :: "r"(half + 1) : "memory");
}

__device__ __forceinline__ unsigned int ld_acquire(unsigned int* p) {
    unsigned int r;
    asm volatile("ld.acquire.gpu.u32 %0, [%1];" : "=r"(r) : "l"(p) : "memory");
    return r;
}
__device__ __forceinline__ void st_release(unsigned int* p, unsigned int v) {
    asm volatile("st.release.gpu.u32 [%0], %1;" :: "l"(p), "r"(v) : "memory");
}

// Tree grid barrier: 8 leaf counters + root + generation. All resident blocks
// call it the same number of times; counters return to zero each use.
__device__ __forceinline__ void grid_sync() {
    __syncthreads();
    if (threadIdx.x == 0) {
        unsigned int gen = ld_acquire(&g_bar_gen);   // stable until all arrive
        int l = blockIdx.x & 7;
        unsigned int lsz = (gridDim.x >> 3) + ((unsigned)l < (gridDim.x & 7u) ? 1u : 0u);
        __threadfence();                             // order phase writes before arrival
        unsigned int t = atomicAdd(&g_leaf[l], 1u);
        if (t == lsz - 1u) {
            g_leaf[l] = 0u;
            __threadfence();
            unsigned int nroot = (gridDim.x < 8u) ? gridDim.x : 8u;
            unsigned int r = atomicAdd(&g_root, 1u);
            if (r == nroot - 1u) {
                g_root = 0u;
                __threadfence();
                st_release(&g_bar_gen, gen + 1u);
            } else {
                while (ld_acquire(&g_bar_gen) == gen) { __nanosleep(16); }
            }
        } else {
            while (ld_acquire(&g_bar_gen) == gen) { __nanosleep(16); }
        }
    }
    __syncthreads();
}

// ---------------------------------------------------------------------------
// Stage store: A (k-major, tf32-converted, scalar scatter) + B (k-major, f4)
// ---------------------------------------------------------------------------
__device__ __forceinline__ void stage_store(float* stage, int am, int akq,
                                            int bkk, int bnq,
                                            float4 Ar0, float4 Ar1,
                                            float4 Br0, float4 Br1)
{
    float* As = stage;
    float* Bs = stage + AS_F;
    As[(akq + 0) * AS_PITCH + am] = f2tf32f(Ar0.x);
    As[(akq + 1) * AS_PITCH + am] = f2tf32f(Ar0.y);
    As[(akq + 2) * AS_PITCH + am] = f2tf32f(Ar0.z);
    As[(akq + 3) * AS_PITCH + am] = f2tf32f(Ar0.w);
    As[(akq + 4) * AS_PITCH + am] = f2tf32f(Ar1.x);
    As[(akq + 5) * AS_PITCH + am] = f2tf32f(Ar1.y);
    As[(akq + 6) * AS_PITCH + am] = f2tf32f(Ar1.z);
    As[(akq + 7) * AS_PITCH + am] = f2tf32f(Ar1.w);
    float4 v0 = make_float4(f2tf32f(Br0.x), f2tf32f(Br0.y),
                            f2tf32f(Br0.z), f2tf32f(Br0.w));
    float4 v1 = make_float4(f2tf32f(Br1.x), f2tf32f(Br1.y),
                            f2tf32f(Br1.z), f2tf32f(Br1.w));
    *(float4*)&Bs[bkk * AS_PITCH + bnq]     = v0;
    *(float4*)&Bs[bkk * AS_PITCH + bnq + 4] = v1;
}

// ---------------------------------------------------------------------------
// GEMM tile via tensor cores (tf32 mma.sync):
//   C[64 x 64] = A[64 x kchunk] * W[kchunk x 64-of-N]
// 256-thread worker = 8 warps; warp (wm = w&3, wn = w>>2) computes the
// m16 slab wm, n32 half wn as 4 x m16n8k8 fragments.
// 2-stage smem double buffer, register prefetch, 1 wbar per ktile.
// ---------------------------------------------------------------------------
__device__ void gemm_tile(int half, int ht, float* sbase,
                          const float* __restrict__ A, int lda,
                          const float* __restrict__ W, int N,
                          float* __restrict__ Pout, int kchunk)
{
    const int lane = ht & 31;
    const int wrp  = ht >> 5;         // 0..7
    const int wm = wrp & 3;           // m16 slab
    const int wn = wrp >> 2;          // n32 half
    const int g = lane >> 2;          // 0..7
    const int t = lane & 3;           // 0..3

    // loader mapping (conflict-free STS for A; coalesced globals)
    const int am  = ht & 63;          // A row 0..63
    const int akq = (ht >> 6) * 8;    // k sub-offset 0,8,16,24
    const int bkk = ht >> 3;          // B k row 0..31
    const int bnq = (ht & 7) * 8;     // B col 0..56

    float acc[4][4];
    #pragma unroll
    for (int f = 0; f < 4; f++)
        #pragma unroll
        for (int i = 0; i < 4; i++) acc[f][i] = 0.0f;

    const int T = kchunk >> 5;
    const float* Abase = A + (size_t)am * lda + akq;
    const float* Wbase = W + (size_t)bkk * N + bnq;

    // load ktile 0 into regs
    float4 Ar0 = ldcg4(Abase);
    float4 Ar1 = ldcg4(Abase + 4);
    float4 Br0 = ldg4(Wbase);
    float4 Br1 = ldg4(Wbase + 4);

    wbar(half);                        // previous smem users done
    stage_store(sbase, am, akq, bkk, bnq, Ar0, Ar1, Br0, Br1);
    if (T > 1) {                       // prefetch ktile 1
        Ar0 = ldcg4(Abase + 32);
        Ar1 = ldcg4(Abase + 36);
        const float* wp = Wbase + 32 * N;
        Br0 = ldg4(wp);
        Br1 = ldg4(wp + 4);
    }
    wbar(half);                        // stage 0 visible

    int p = 0;
    for (int tt = 0; tt < T; tt++) {
        const float* As = sbase + p * STAGE_F;
        const float* Bs = As + AS_F;
        const float* Ab = As + wm * 16;
        const float* Bb = Bs + wn * 32;
        #pragma unroll
        for (int q = 0; q < 4; q++) {
            const int kr = q * 8 + t;
            uint32_t a0 = __float_as_uint(Ab[kr * AS_PITCH + g]);
            uint32_t a1 = __float_as_uint(Ab[kr * AS_PITCH + g + 8]);
            uint32_t a2 = __float_as_uint(Ab[(kr + 4) * AS_PITCH + g]);
            uint32_t a3 = __float_as_uint(Ab[(kr + 4) * AS_PITCH + g + 8]);
            #pragma unroll
            for (int f = 0; f < 4; f++) {
                uint32_t b0 = __float_as_uint(Bb[kr * AS_PITCH + f * 8 + g]);
                uint32_t b1 = __float_as_uint(Bb[(kr + 4) * AS_PITCH + f * 8 + g]);
                mma_tf32(acc[f], a0, a1, a2, a3, b0, b1);
            }
        }

        if (tt + 1 < T) {
            stage_store(sbase + (1 - p) * STAGE_F, am, akq, bkk, bnq,
                        Ar0, Ar1, Br0, Br1);
            if (tt + 2 < T) {
                int kb = (tt + 2) << 5;
                Ar0 = ldcg4(Abase + kb);
                Ar1 = ldcg4(Abase + kb + 4);
                const float* wp = Wbase + (size_t)kb * N;
                Br0 = ldg4(wp);
                Br1 = ldg4(wp + 4);
            }
            wbar(half);
            p ^= 1;
        }
    }

    // epilogue: frag (row g / g+8, cols 2t, 2t+1)
    const int row0 = wm * 16 + g;
    float* r0p = Pout + (size_t)row0 * N;
    float* r1p = r0p + 8 * N;
    #pragma unroll
    for (int f = 0; f < 4; f++) {
        int col = wn * 32 + f * 8 + 2 * t;
        stcg2(r0p + col, make_float2(acc[f][0], acc[f][1]));
        stcg2(r1p + col, make_float2(acc[f][2], acc[f][3]));
    }
}

// X1 slot tables. Pairs: p0=[e1|e2], p1=[e0|e2], p2=[e0|e1]
__device__ __constant__ int D1ROW[3] = {1, 0, 0};
__device__ __constant__ int D1OFF[3] = {0, 0, 768};
__device__ __constant__ int D2ROW[3] = {2, 2, 1};
__device__ __constant__ int D2OFF[3] = {0, 768, 768};

// ---------------------------------------------------------------------------
// Maxpool job: job = bk*3 + q; bk = (b,k), q = 256-col chunk.
// 256 threads = 4 row-groups x 64 float4-columns.
// ---------------------------------------------------------------------------
__device__ void maxpool_job(int half, int t, float* sb, int job,
                            const float* __restrict__ enc,
                            const int* __restrict__ ep,
                            const float* __restrict__ projW)
{
    int bk = job / 3, q = job - bk * 3;
    int b = bk / 3, k = bk - b * 3;
    int s0 = ep[bk * 2 + 0];
    int s1 = ep[bk * 2 + 1];

    const int rg = t >> 6;            // row group 0..3
    const int c4 = t & 63;            // float4 col in chunk

    const float* base = enc + (size_t)b * SEQ * DIM + q * 256 + c4 * 4;
    float4 m = make_float4(-1e30f, -1e30f, -1e30f, -1e30f);
    #pragma unroll 4
    for (int s = s0 + rg; s <= s1; s += 4) {
        float4 v = ldg4(base + (size_t)s * DIM);
        m.x = fmaxf(m.x, v.x); m.y = fmaxf(m.y, v.y);
        m.z = fmaxf(m.z, v.z); m.w = fmaxf(m.w, v.w);
    }

    wbar(half);                        // protect smem from prior job
    float4* sm = reinterpret_cast<float4*>(sb);   // 256 float4 = 4 KB
    sm[t] = m;
    wbar(half);

    if (rg == 0) {
        float4 m1 = sm[t + 64], m2 = sm[t + 128], m3 = sm[t + 192];
        m.x = fmaxf(fmaxf(m.x, m1.x), fmaxf(m2.x, m3.x));
        m.y = fmaxf(fmaxf(m.y, m1.y), fmaxf(m2.y, m3.y));
        m.z = fmaxf(fmaxf(m.z, m1.z), fmaxf(m2.z, m3.z));
        m.w = fmaxf(fmaxf(m.w, m1.w), fmaxf(m2.w, m3.w));

        int d0 = q * 256 + c4 * 4;
        stcg4(g_ent + (size_t)b * PREDK + k * DIM + d0, m);
        stcg4(g_e   + (size_t)(k * 64 + b) * DIM + d0, m);
        stcg4(g_X1  + (size_t)(D1ROW[k] * 64 + b) * KDIM + D1OFF[k] + d0, m);
        stcg4(g_X1  + (size_t)(D2ROW[k] * 64 + b) * KDIM + D2OFF[k] + d0, m);
        stcg4(g_X2  + (size_t)(k * 64 + b) * KDIM + 768 + d0, m);

        float4 pw = ldg4(projW + d0);
        float dv = m.x * pw.x + m.y * pw.y + m.z * pw.z + m.w * pw.w;
        #pragma unroll
        for (int off = 16; off > 0; off >>= 1)
            dv += __shfl_down_sync(0xffffffffu, dv, off);
        if ((t & 31) == 0) sb[1024 + (t >> 5)] = dv;   // slots 0,1
    }
    wbar(half);
    if (t == 0) __stcg(g_scorep + job, sb[1024] + sb[1025]);
    wbar(half);
}

// ---------------------------------------------------------------------------
// finish1: fc1 reduce + relu + fc2 + sigmoid + Ar + u -> X2 left half
// ---------------------------------------------------------------------------
__device__ void finish1_job(int half, int t, float* sb, int r,
                            const float* __restrict__ b1,
                            const float* __restrict__ W2, const float* __restrict__ b2,
                            const float* __restrict__ ArW, const float* __restrict__ Arb)
{
    float* sh_h = sb;                  // 512
    float* red  = sb + 512;            // 8 warps * 5
    float* sh_s = sb + 560;            // 8

    wbar(half);                        // protect smem from previous job
    for (int j = t; j < 512; j += 256) {
        float s = b1[j];
        #pragma unroll
        for (int z = 0; z < KS_FC1; z++)
            s += __ldcg(g_pfc1 + (size_t)z * FC1_MN + r * 512 + j);
        sh_h[j] = fmaxf(s, 0.0f);
    }
    wbar(half);

    float ps[5] = {0, 0, 0, 0, 0};
    for (int j = t; j < 512; j += 256) {
        float h = sh_h[j];
        #pragma unroll
        for (int c = 0; c < 5; c++) ps[c] += h * W2[j * 5 + c];
    }
    #pragma unroll
    for (int off = 16; off > 0; off >>= 1) {
        #pragma unroll
        for (int c = 0; c < 5; c++)
            ps[c] += __shfl_down_sync(0xffffffffu, ps[c], off);
    }
    if ((t & 31) == 0) {
        int w = t >> 5;
        #pragma unroll
        for (int c = 0; c < 5; c++) red[w * 5 + c] = ps[c];
    }
    wbar(half);
    if (t < 5) {
        float s = 0.0f;
        #pragma unroll
        for (int w = 0; w < 8; w++) s += red[w * 5 + t];
        sh_s[t] = sigmoidf(s + b2[t]);
    }
    wbar(half);

    float s0 = sh_s[0], s1 = sh_s[1], s2 = sh_s[2], s3 = sh_s[3], s4 = sh_s[4];
    const float* epv = g_e + (size_t)r * DIM;
    float* up = g_X2 + (size_t)r * KDIM;          // u -> left half of X2
    for (int d = t; d < DIM; d += 256) {
        float a = Arb[d] + s0 * ArW[d] + s1 * ArW[DIM + d] + s2 * ArW[2 * DIM + d]
                + s3 * ArW[3 * DIM + d] + s4 * ArW[4 * DIM + d];
        __stcg(up + d, a * __ldcg(epv + d));
    }
}

__device__ void pred_finish_job(int half, int t, float* sb, int b,
                                const float* __restrict__ b1,
                                const float* __restrict__ W2,
                                const float* __restrict__ b2,
                                float* __restrict__ rel_out)
{
    float* sh_h = sb;
    float* red  = sb + 512;

    wbar(half);
    for (int j = t; j < 512; j += 256) {
        float s = b1[j];
        #pragma unroll
        for (int z = 0; z < KS_PRED; z++)
            s += __ldcg(g_ppred + (size_t)z * PRED_MN + b * 512 + j);
        sh_h[j] = fmaxf(s, 0.0f);
    }
    wbar(half);

    float ps[5] = {0, 0, 0, 0, 0};
    for (int j = t; j < 512; j += 256) {
        float h = sh_h[j];
        #pragma unroll
        for (int c = 0; c < 5; c++) ps[c] += h * W2[j * 5 + c];
    }
    #pragma unroll
    for (int off = 16; off > 0; off >>= 1) {
        #pragma unroll
        for (int c = 0; c < 5; c++)
            ps[c] += __shfl_down_sync(0xffffffffu, ps[c], off);
    }
    if ((t & 31) == 0) {
        int w = t >> 5;
        #pragma unroll
        for (int c = 0; c < 5; c++) red[w * 5 + c] = ps[c];
    }
    wbar(half);
    if (t < 5) {
        float s = 0.0f;
        #pragma unroll
        for (int w = 0; w < 8; w++) s += red[w * 5 + t];
        rel_out[b * 5 + t] = s + b2[t];
    }
}

// ---------------------------------------------------------------------------
// Persistent fused kernel: 512 threads = two 256-thread workers
// ---------------------------------------------------------------------------
__global__ void __launch_bounds__(512, 1)
fused_kernel(const float* __restrict__ enc, const int* __restrict__ ep,
             const float* __restrict__ ArW, const float* __restrict__ Arb,
             const float* __restrict__ VrW1, const float* __restrict__ Vrb1,
             const float* __restrict__ VrW2, const float* __restrict__ Vrb2,
             const float* __restrict__ gateW, const float* __restrict__ gateb,
             const float* __restrict__ predW1, const float* __restrict__ predb1,
             const float* __restrict__ predW2, const float* __restrict__ predb2,
             const float* __restrict__ projW, const float* __restrict__ projb,
             float* __restrict__ out_rel, float* __restrict__ out_score,
             float* __restrict__ out_final)
{
    extern __shared__ __align__(16) float smem_u[];

    const int half = threadIdx.x >> 8;
    const int ht   = threadIdx.x & 255;
    float* sbase = smem_u + half * WORKER_F;

    const int nb = gridDim.x;
    const int wid     = blockIdx.x * 2 + half;
    const int wstride = 2 * nb;              // 296 workers

    // ---- Phase 0: span max-pool (576 chunk jobs; scores partial) ----
    for (int job = wid; job < 576; job += wstride)
        maxpool_job(half, ht, sbase, job, enc, ep, projW);
    grid_sync();

    for (int it = 0; it < 5; it++) {
        // ---- P1: fc1 GEMM partials (288) + pred GEMM (96, iter 0) ----
        int nj = (it == 0) ? (288 + 96) : 288;
        for (int job = wid; job < nj; job += wstride) {
            if (job < 288) {
                int z = job / 24, rem = job % 24;
                int m0 = (rem >> 3) * 64, n0 = (rem & 7) * 64;
                int k0 = z * 128;
                gemm_tile(half, ht, sbase,
                          g_X1 + (size_t)m0 * KDIM + k0, KDIM,
                          VrW1 + (size_t)k0 * 512 + n0, 512,
                          g_pfc1 + (size_t)z * FC1_MN + m0 * 512 + n0, 128);
            } else {
                int j = job - 288;                 // 0..95
                int z = j >> 3, n0 = (j & 7) * 64;
                int k0 = z * 192;
                gemm_tile(half, ht, sbase,
                          g_ent + k0, PREDK,
                          predW1 + (size_t)k0 * 512 + n0, 512,
                          g_ppred + (size_t)z * PRED_MN + n0, 192);
            }
        }
        grid_sync();

        // ---- P2: fc1 finish -> u (+ pred finish & score finish on iter 0) ----
        nj = (it == 0) ? 257 : 192;
        for (int job = wid; job < nj; job += wstride) {
            if (job < 192) {
                finish1_job(half, ht, sbase, job, Vrb1, VrW2, Vrb2, ArW, Arb);
            } else if (job < 256) {
                pred_finish_job(half, ht, sbase, job - 192,
                                predb1, predW2, predb2, out_rel);
            } else {
                // score finish: 192 entity scores from 3 partials each
                if (ht < 192) {
                    float s = __ldcg(g_scorep + ht * 3 + 0)
                            + __ldcg(g_scorep + ht * 3 + 1)
                            + __ldcg(g_scorep + ht * 3 + 2);
                    out_score[ht] = sigmoidf(s + projb[0]);
                }
            }
        }
        grid_sync();

        // ---- P3: gate GEMM partials (288) ----
        for (int job = wid; job < 288; job += wstride) {
            int z = job / 36, rem = job % 36;
            int m0 = (rem / 12) * 64, n0 = (rem % 12) * 64;
            int k0 = z * 192;
            gemm_tile(half, ht, sbase,
                      g_X2 + (size_t)m0 * KDIM + k0, KDIM,
                      gateW + (size_t)k0 * 768 + n0, 768,
                      g_pgate + (size_t)z * GATE_MN + m0 * 768 + n0, 192);
        }
        grid_sync();

        // ---- P4: gate blend; in-place e update + X1/X2 scatter ----
        bool last = (it == 4);
        int tg = blockIdx.x * 512 + threadIdx.x;
        for (int q = tg; q < GATE_MN / 4; q += nb * 512) {
            int idx = q * 4;
            int r = idx / 768, n = idx - r * 768;
            int p = r >> 6, b = r & 63;
            float4 s = *(const float4*)(gateb + n);
            #pragma unroll
            for (int z = 0; z < KS_GATE; z++) {
                float4 pv = ldcg4(g_pgate + (size_t)z * GATE_MN + idx);
                s.x += pv.x; s.y += pv.y; s.z += pv.z; s.w += pv.w;
            }
            float4 uv = ldcg4(g_X2 + (size_t)r * KDIM + n);   // u (left half)
            float4 ev = ldcg4(g_e + idx);
            float4 res; float gg;
            gg = sigmoidf(s.x); res.x = gg * ev.x + (1.0f - gg) * uv.x;
            gg = sigmoidf(s.y); res.y = gg * ev.y + (1.0f - gg) * uv.y;
            gg = sigmoidf(s.z); res.z = gg * ev.z + (1.0f - gg) * uv.z;
            gg = sigmoidf(s.w); res.w = gg * ev.w + (1.0f - gg) * uv.w;
            if (last) {
                *(float4*)(out_final + (size_t)b * PREDK + p * DIM + n) = res;
            } else {
                stcg4(g_e + idx, res);
                stcg4(g_X2 + (size_t)r * KDIM + 768 + n, res);
                stcg4(g_X1 + (size_t)(D1ROW[p] * 64 + b) * KDIM + D1OFF[p] + n, res);
                stcg4(g_X1 + (size_t)(D2ROW[p] * 64 + b) * KDIM + D2OFF[p] + n, res);
            }
        }
        if (!last) grid_sync();
    }
}

// ---------------------------------------------------------------------------
// Launcher
// ---------------------------------------------------------------------------
extern "C" void kernel_launch(void* const* d_in, const int* in_sizes, int n_in,
                              void* d_out, int out_size)
{
    const float* encoding = (const float*)d_in[0];
    const int*   ent_pos  = (const int*)  d_in[1];
    const float* Ar_W     = (const float*)d_in[2];
    const float* Ar_b     = (const float*)d_in[3];
    const float* Vr_W1    = (const float*)d_in[4];
    const float* Vr_b1    = (const float*)d_in[5];
    const float* Vr_W2    = (const float*)d_in[6];
    const float* Vr_b2    = (const float*)d_in[7];
    const float* gate_W   = (const float*)d_in[8];
    const float* gate_b   = (const float*)d_in[9];
    const float* pred_W1  = (const float*)d_in[10];
    const float* pred_b1  = (const float*)d_in[11];
    const float* pred_W2  = (const float*)d_in[12];
    const float* pred_b2  = (const float*)d_in[13];
    const float* proj_W   = (const float*)d_in[14];
    const float* proj_b   = (const float*)d_in[15];

    float* out = (float*)d_out;
    float* out_rel   = out;              // (64,5)
    float* out_score = out + 320;        // (64,3)
    float* out_final = out + 512;        // (64,3,768)

    int dev = 0;
    cudaGetDevice(&dev);
    int sms = 148;
    cudaDeviceGetAttribute(&sms, cudaDevAttrMultiProcessorCount, dev);

    cudaFuncSetAttribute(fused_kernel,
                         cudaFuncAttributeMaxDynamicSharedMemorySize,
                         TOTAL_SMEM_B);

    fused_kernel<<<sms, 512, TOTAL_SMEM_B>>>(
        encoding, ent_pos, Ar_W, Ar_b,
        Vr_W1, Vr_b1, Vr_W2, Vr_b2,
        gate_W, gate_b,
        pred_W1, pred_b1, pred_W2, pred_b2,
        proj_W, proj_b,
        out_rel, out_score, out_final);

    (void)in_sizes; (void)n_in; (void)out_size;
}